// round 11
// baseline (speedup 1.0000x reference)
#include <cuda_runtime.h>
#include <math.h>
#include <stdint.h>

// ---------------------------------------------------------------------------
// Cond_NCP_CfC: 3 chained CfC cells, B=128, T=512.
// Persistent kernel: 8 batch-tiles x 16 CTAs; weights SMEM-resident; gates
// 2+3 merged (sigmoid(a+b) trick); 2 intra-tile global barriers per step.
// ---------------------------------------------------------------------------

#define TSTEPS 512
#define BATCH  128
#define H0N    152
#define H1N    101
#define K0     664        // 512 inputs + 152 h0
#define K0V    166        // K0/4
#define XCS0   167        // xc0 row stride (float4), bank-disjoint
#define K1     253        // 152 + 101
#define W1SF   264        // w1 row stride in floats (66 float4), zero-padded
#define K1V    64         // padded K1 in float4 (256 floats)
#define XCS1   67         // xc1 row stride (float4)
#define K2     104        // 101 + 3
#define K2V    26
#define NTILES 8

// smem layout (bytes)
#define OFF_W0   0          // [30][166] float4 = 79680
#define OFF_W1   79680      // [21][66]  float4 = 22176
#define OFF_W2   101856     // [9][26]   float4 = 3744
#define OFF_XC0  105600     // [16][167] float4 = 42752
#define OFF_XC1  148352     // [16][67]  float4 = 17152
#define OFF_XC2  165504     // [16][26]  float4 = 6656
#define OFF_PRE0 172160     // [30][16] float = 1920
#define OFF_PRE1 174080     // [21][16] float = 1344
#define OFF_PRE2 175424     // [9][16]  float = 576
#define OFF_B0   176000     // 30 floats
#define OFF_B1   176120     // 21 floats
#define OFF_B2   176204     // 9 floats
#define OFF_H2   176240     // [2][16][3] floats = 384
#define SMEM_BYTES 176640

// device-global scratch (no allocations allowed)
__device__ float g_h0[2][BATCH][152];   // double-buffered hidden, layer 0
__device__ float g_h1[2][BATCH][104];   // layer 1, padded 101->104 (pad = 0)
__device__ int           g_cnt[NTILES];
__device__ volatile int  g_gen[NTILES];

__device__ __forceinline__ float sigm(float x) { return 1.0f / (1.0f + expf(-x)); }

__device__ __forceinline__ void tile_barrier(int tile, int& gen) {
    __syncthreads();
    if (threadIdx.x == 0) {
        __threadfence();                      // publish h writes
        int g = gen;
        if (atomicAdd(&g_cnt[tile], 1) == 15) {
            g_cnt[tile] = 0;
            __threadfence();
            g_gen[tile] = g + 1;
        } else {
            while (g_gen[tile] == g) { }
        }
        __threadfence();                      // acquire
    }
    __syncthreads();
    gen++;
}

__global__ void __launch_bounds__(256, 1)
ncp_cfc_kernel(const float* __restrict__ features, const float* __restrict__ command,
               const float* __restrict__ l0W, const float* __restrict__ l0b,
               const float* __restrict__ l1W, const float* __restrict__ l1b,
               const float* __restrict__ l2W, const float* __restrict__ l2b,
               const float* __restrict__ m0, const float* __restrict__ m1,
               const float* __restrict__ m2,
               float* __restrict__ out, int out_size)
{
    extern __shared__ unsigned char smem[];
    float4* w0s  = (float4*)(smem + OFF_W0);
    float4* w1s  = (float4*)(smem + OFF_W1);
    float4* w2s  = (float4*)(smem + OFF_W2);
    float4* xc0  = (float4*)(smem + OFF_XC0);
    float4* xc1  = (float4*)(smem + OFF_XC1);
    float4* xc2  = (float4*)(smem + OFF_XC2);
    float*  pre0 = (float*)(smem + OFF_PRE0);
    float*  pre1 = (float*)(smem + OFF_PRE1);
    float*  pre2 = (float*)(smem + OFF_PRE2);
    float*  b0s  = (float*)(smem + OFF_B0);
    float*  b1s  = (float*)(smem + OFF_B1);
    float*  b2s  = (float*)(smem + OFF_B2);
    float*  h2s  = (float*)(smem + OFF_H2);   // [parity*16 + b]*3 + j

    const int tid  = threadIdx.x;
    const int cta  = blockIdx.x;
    const int tile = cta >> 4;
    const int r    = cta & 15;
    const int gb   = tile * 16;               // global batch base of this tile

    // neuron slice ownership (layer0: 8x10 + 8x9 = 152; layer1: 5x7 + 11x6 = 101)
    const int n0c = (r < 8) ? 10 : 9;
    const int n0b = (r < 8) ? r * 10 : 80 + (r - 8) * 9;
    const int n1c = (r < 5) ? 7 : 6;
    const int n1b = (r < 5) ? r * 7 : 35 + (r - 5) * 6;
    const int NR0 = n0c * 3;                  // merged gate rows (ff1, ff2, a+b)
    const int NR1 = n1c * 3;

    int gen = g_gen[tile];                    // stable leftover from prior launch

    // ---------------- prologue: weights -> smem (masked, gate-merged) -------
    for (int i = tid; i < NR0 * K0V; i += 256) {
        int row = i / K0V, k = i - row * K0V;
        int ln = row / 3, g = row - ln * 3, n = n0b + ln;
        float4 w;
        if (g < 2) {
            w = ((const float4*)(l0W + ((size_t)g * H0N + n) * K0))[k];
            float4 m = ((const float4*)(m0 + (size_t)n * K0))[k];
            w.x *= m.x; w.y *= m.y; w.z *= m.z; w.w *= m.w;
        } else {
            float4 a = ((const float4*)(l0W + ((size_t)2 * H0N + n) * K0))[k];
            float4 c = ((const float4*)(l0W + ((size_t)3 * H0N + n) * K0))[k];
            w.x = a.x + c.x; w.y = a.y + c.y; w.z = a.z + c.z; w.w = a.w + c.w;
        }
        w0s[row * K0V + k] = w;
    }
    for (int i = tid; i < NR1 * W1SF; i += 256) {
        int row = i / W1SF, k = i - row * W1SF;
        int ln = row / 3, g = row - ln * 3, n = n1b + ln;
        float w = 0.0f;
        if (k < K1) {
            if (g < 2) w = l1W[((size_t)g * H1N + n) * K1 + k] * m1[(size_t)n * K1 + k];
            else       w = l1W[((size_t)2 * H1N + n) * K1 + k] +
                           l1W[((size_t)3 * H1N + n) * K1 + k];
        }
        ((float*)w1s)[row * W1SF + k] = w;
    }
    if (tid < NR0) {
        int ln = tid / 3, g = tid - ln * 3, n = n0b + ln;
        b0s[tid] = (g < 2) ? l0b[g * H0N + n] : (l0b[2 * H0N + n] + l0b[3 * H0N + n]);
    }
    if (tid < NR1) {
        int ln = tid / 3, g = tid - ln * 3, n = n1b + ln;
        b1s[tid] = (g < 2) ? l1b[g * H1N + n] : (l1b[2 * H1N + n] + l1b[3 * H1N + n]);
    }
    if (r == 15) {
        for (int i = tid; i < 9 * K2; i += 256) {
            int row = i / K2, k = i - row * K2;
            int n = row / 3, g = row - n * 3;
            float w;
            if (g < 2) w = l2W[(g * 3 + n) * K2 + k] * m2[n * K2 + k];
            else       w = l2W[(2 * 3 + n) * K2 + k] + l2W[(3 * 3 + n) * K2 + k];
            ((float*)w2s)[row * K2 + k] = w;
        }
        if (tid < 9) {
            int n = tid / 3, g = tid - n * 3;
            b2s[tid] = (g < 2) ? l2b[g * 3 + n] : (l2b[2 * 3 + n] + l2b[3 * 3 + n]);
        }
        if (tid < 96) h2s[tid] = 0.0f;        // both parities of h2
        for (int i = tid; i < 2 * 16 * 3; i += 256) {  // zero h1 pads, both parities
            int p = i / 48, b = (i / 3) & 15, j = i % 3;
            g_h1[p][gb + b][101 + j] = 0.0f;
        }
    }
    // zero the "prev" (parity 1) hidden slices this CTA owns
    for (int i = tid; i < n0c * 16; i += 256) {
        int n = i >> 4, b = i & 15;
        g_h0[1][gb + b][n0b + n] = 0.0f;
    }
    for (int i = tid; i < n1c * 16; i += 256) {
        int n = i >> 4, b = i & 15;
        g_h1[1][gb + b][n1b + n] = 0.0f;
    }
    tile_barrier(tile, gen);                  // all init visible tile-wide

    const int rt = tid >> 3;                  // row slot 0..31
    const int bt = tid & 7;                   // batch slot (handles bt and bt+8)

    // ---------------- time loop --------------------------------------------
    for (int t = 0; t < TSTEPS; ++t) {
        const int wp = t & 1, rp = wp ^ 1;

        // build xc0 = [features | command | h0_prev]  (166 float4 per batch)
        for (int i = tid; i < 16 * K0V; i += 256) {
            int b = i / K0V, k = i - b * K0V;
            float4 v;
            if (k < 127)
                v = ((const float4*)(features + ((size_t)(gb + b) * TSTEPS + t) * 508))[k];
            else if (k == 127)
                v = *((const float4*)(command + ((size_t)(gb + b) * TSTEPS + t) * 4));
            else
                v = __ldcg((const float4*)&g_h0[rp][gb + b][0] + (k - 128));
            xc0[b * XCS0 + k] = v;
        }
        __syncthreads();

        // layer-0 dots: row rt, batches bt and bt+8
        if (rt < NR0) {
            float a0 = b0s[rt], a1 = a0;
            const float4* __restrict__ wr = w0s + rt * K0V;
            const float4* __restrict__ x0 = xc0 + bt * XCS0;
            const float4* __restrict__ x1 = x0 + 8 * XCS0;
            #pragma unroll 2
            for (int k = 0; k < K0V; ++k) {
                float4 w = wr[k], p = x0[k], q = x1[k];
                a0 = fmaf(w.x, p.x, fmaf(w.y, p.y, fmaf(w.z, p.z, fmaf(w.w, p.w, a0))));
                a1 = fmaf(w.x, q.x, fmaf(w.y, q.y, fmaf(w.z, q.z, fmaf(w.w, q.w, a1))));
            }
            pre0[rt * 16 + bt] = a0;
            pre0[rt * 16 + bt + 8] = a1;
        }
        __syncthreads();

        // combine layer 0 -> h0[wp]
        if (tid < n0c * 16) {
            int n = tid >> 4, b = tid & 15;
            float f1 = tanhf(pre0[(n * 3 + 0) * 16 + b]);
            float f2 = tanhf(pre0[(n * 3 + 1) * 16 + b]);
            float ti = sigm(pre0[(n * 3 + 2) * 16 + b]);
            __stcg(&g_h0[wp][gb + b][n0b + n], f1 + ti * (f2 - f1));
        }
        tile_barrier(tile, gen);              // h0 complete

        // build xc1 = [h0_new | h1_prev(padded)]
        for (int i = tid; i < 16 * K1V; i += 256) {
            int b = i >> 6, k = i & 63;
            float4 v = (k < 38)
                ? __ldcg((const float4*)&g_h0[wp][gb + b][0] + k)
                : __ldcg((const float4*)&g_h1[rp][gb + b][0] + (k - 38));
            xc1[b * XCS1 + k] = v;
        }
        __syncthreads();

        // layer-1 dots
        if (rt < NR1) {
            float a0 = b1s[rt], a1 = a0;
            const float4* __restrict__ wr = w1s + rt * 66;
            const float4* __restrict__ x0 = xc1 + bt * XCS1;
            const float4* __restrict__ x1 = x0 + 8 * XCS1;
            #pragma unroll 4
            for (int k = 0; k < K1V; ++k) {
                float4 w = wr[k], p = x0[k], q = x1[k];
                a0 = fmaf(w.x, p.x, fmaf(w.y, p.y, fmaf(w.z, p.z, fmaf(w.w, p.w, a0))));
                a1 = fmaf(w.x, q.x, fmaf(w.y, q.y, fmaf(w.z, q.z, fmaf(w.w, q.w, a1))));
            }
            pre1[rt * 16 + bt] = a0;
            pre1[rt * 16 + bt + 8] = a1;
        }
        __syncthreads();

        // combine layer 1 -> h1[wp]
        if (tid < n1c * 16) {
            int n = tid >> 4, b = tid & 15;
            float f1 = tanhf(pre1[(n * 3 + 0) * 16 + b]);
            float f2 = tanhf(pre1[(n * 3 + 1) * 16 + b]);
            float ti = sigm(pre1[(n * 3 + 2) * 16 + b]);
            __stcg(&g_h1[wp][gb + b][n1b + n], f1 + ti * (f2 - f1));
        }
        tile_barrier(tile, gen);              // h1 complete

        // layer 2 + controls: CTA 15 only (h2 private in smem; no 3rd barrier)
        if (r == 15) {
            for (int i = tid; i < 16 * K2V; i += 256) {
                int b = i / K2V, k = i - b * K2V;
                xc2[b * K2V + k] = __ldcg((const float4*)&g_h1[wp][gb + b][0] + k);
            }
            __syncthreads();
            if (tid < 48) {                   // overwrite pad with h2_prev
                int b = tid / 3, j = tid - b * 3;
                ((float*)xc2)[b * K2 + 101 + j] = h2s[(rp * 16 + b) * 3 + j];
            }
            __syncthreads();
            if (tid < 144) {
                int row = tid / 16, b = tid & 15;
                float a = b2s[row];
                const float4* wr = w2s + row * K2V;
                const float4* xr = xc2 + b * K2V;
                #pragma unroll
                for (int k = 0; k < K2V; ++k) {
                    float4 w = wr[k], x = xr[k];
                    a = fmaf(w.x, x.x, fmaf(w.y, x.y, fmaf(w.z, x.z, fmaf(w.w, x.w, a))));
                }
                pre2[row * 16 + b] = a;
            }
            __syncthreads();
            if (tid < 48) {
                int n = tid >> 4, b = tid & 15;
                float f1 = tanhf(pre2[(n * 3 + 0) * 16 + b]);
                float f2 = tanhf(pre2[(n * 3 + 1) * 16 + b]);
                float ti = sigm(pre2[(n * 3 + 2) * 16 + b]);
                float h = f1 + ti * (f2 - f1);
                h2s[(wp * 16 + b) * 3 + n] = h;
                float c = (n == 0) ? tanhf(h) : sigm(h);
                out[((size_t)(gb + b) * TSTEPS + t) * 3 + n] = c;
            }
            __syncthreads();
        }
    }

    // ---------------- epilogue: hx = concat(h0, h1, h2) at parity 1 --------
    if (out_size >= 229376) {
        float* hx = out + (size_t)BATCH * TSTEPS * 3;
        for (int i = tid; i < n0c * 16; i += 256) {
            int n = i >> 4, b = i & 15;
            hx[(size_t)(gb + b) * 256 + n0b + n] = __ldcg(&g_h0[1][gb + b][n0b + n]);
        }
        for (int i = tid; i < n1c * 16; i += 256) {
            int n = i >> 4, b = i & 15;
            hx[(size_t)(gb + b) * 256 + 152 + n1b + n] = __ldcg(&g_h1[1][gb + b][n1b + n]);
        }
        if (r == 15 && tid < 48) {
            int b = tid / 3, j = tid - b * 3;
            hx[(size_t)(gb + b) * 256 + 253 + j] = h2s[(1 * 16 + b) * 3 + j];
        }
    }
}

extern "C" void kernel_launch(void* const* d_in, const int* in_sizes, int n_in,
                              void* d_out, int out_size) {
    (void)in_sizes; (void)n_in;
    cudaFuncSetAttribute(ncp_cfc_kernel,
                         cudaFuncAttributeMaxDynamicSharedMemorySize, SMEM_BYTES);
    ncp_cfc_kernel<<<128, 256, SMEM_BYTES>>>(
        (const float*)d_in[0], (const float*)d_in[1],
        (const float*)d_in[2], (const float*)d_in[3],
        (const float*)d_in[4], (const float*)d_in[5],
        (const float*)d_in[6], (const float*)d_in[7],
        (const float*)d_in[8], (const float*)d_in[9],
        (const float*)d_in[10],
        (float*)d_out, out_size);
}

// round 16
// speedup vs baseline: 1.5834x; 1.5834x over previous
#include <cuda_runtime.h>
#include <math.h>
#include <stdint.h>

// ---------------------------------------------------------------------------
// Cond_NCP_CfC: 3 chained CfC cells, B=128, T=512.
// Persistent kernel, 8 batch-tiles x 16 CTAs (1 CTA/SM), 512 thr/CTA.
// Weights SMEM-resident; gates 2+3 merged; ONE tile barrier per step;
// layer-2 pipelined one step behind on CTA15; cp.async feature prefetch;
// triple-buffered hidden state; K-split dot products.
// ---------------------------------------------------------------------------

#define TSTEPS 512
#define NT     512
#define NTILES 8
#define H0N    152
#define H1N    101

#define FEAT_S 129      // f4 stride, 128 used (508 feat + 4 cmd)
#define H0B_S  39       // f4 stride, 38 used (152 floats)
#define XC1_S  67       // f4 stride, 64 used (256 floats, padded 253)
#define XC2_S  27       // f4 stride, 26 used (104 floats)
#define W0_S   166      // f4 per row (664 floats)
#define W1_S   66       // f4 per row (264 floats, padded 253)

// smem offsets (bytes)
#define OFF_W0   0        // 30 x 166 f4 = 79680
#define OFF_W1   79680    // 21 x 66  f4 = 22176
#define OFF_W2   101856   // 9  x 26  f4 = 3744
#define OFF_FEAT 105600   // 2 x 16 x 129 f4 = 66048
#define OFF_H0B  171648   // 16 x 39 f4 = 9984
#define OFF_XC1  181632   // 16 x 67 f4 = 17152
#define OFF_XC2  198784   // 16 x 27 f4 = 6912
#define OFF_PRE0 205696   // 2 x 30 x 16 fl = 3840
#define OFF_PRE1 209536   // 2 x 21 x 16 fl = 2688
#define OFF_PRE2 212224   // 9 x 16 fl = 576
#define OFF_B0   212800   // 120
#define OFF_B1   212928   // 84
#define OFF_B2   213024   // 36
#define OFF_H2   213072   // 2 x 16 x 3 fl = 384
#define SMEM_BYTES 213504

// device-global scratch (no allocations allowed)
__device__ float g_h0[3][128][152];   // triple-buffered hidden, layer 0
__device__ float g_h1[3][128][104];   // layer 1, padded 101->104 (pads = 0)
__device__ int           g_cnt[NTILES];
__device__ volatile int  g_gen[NTILES];

__device__ __forceinline__ float sigm(float x) {
    return __fdividef(1.0f, 1.0f + __expf(-x));
}
__device__ __forceinline__ float tanh_(float x) {
    return 1.0f - __fdividef(2.0f, __expf(2.0f * x) + 1.0f);
}
__device__ __forceinline__ void cp16(void* s, const void* g) {
    uint32_t sa = (uint32_t)__cvta_generic_to_shared(s);
    asm volatile("cp.async.cg.shared.global [%0], [%1], 16;\n" :: "r"(sa), "l"(g));
}

__device__ __forceinline__ void tile_barrier(int tile, int& gen) {
    __syncthreads();
    if (threadIdx.x == 0) {
        __threadfence();
        int g = gen;
        if (atomicAdd(&g_cnt[tile], 1) == 15) {
            g_cnt[tile] = 0;
            __threadfence();
            g_gen[tile] = g + 1;
        } else {
            while (g_gen[tile] == g) { }
        }
        __threadfence();
    }
    __syncthreads();
    gen++;
}

// layer-2 + control outputs for step s (CTA15 only; whole CTA enters).
__device__ __forceinline__ void layer2(int s, int h1buf, int gb, int tid,
                                       float4* xc2, float* pre2,
                                       const float4* w2s, const float* b2s,
                                       float* h2s, float* __restrict__ out)
{
    int hp = (s + 1) & 1;                       // parity holding h2(s-1)
    for (int i = tid; i < 16 * 26; i += NT) {
        int b = i / 26, k = i - b * 26;
        xc2[b * XC2_S + k] = __ldcg((const float4*)&g_h1[h1buf][gb + b][0] + k);
    }
    __syncthreads();
    if (tid < 48) {                             // pad lanes <- h2 prev
        int b = tid / 3, j = tid - b * 3;
        ((float*)xc2)[b * (XC2_S * 4) + 101 + j] = h2s[(hp * 16 + b) * 3 + j];
    }
    __syncthreads();
    if (tid < 144) {
        int row = tid >> 4, b = tid & 15;
        float4 a = {0.f, 0.f, 0.f, 0.f};
        const float4* wr = w2s + row * 26;
        const float4* xr = xc2 + b * XC2_S;
        #pragma unroll
        for (int k = 0; k < 26; ++k) {
            float4 w = wr[k], x = xr[k];
            a.x = fmaf(w.x, x.x, a.x); a.y = fmaf(w.y, x.y, a.y);
            a.z = fmaf(w.z, x.z, a.z); a.w = fmaf(w.w, x.w, a.w);
        }
        pre2[row * 16 + b] = b2s[row] + (a.x + a.y) + (a.z + a.w);
    }
    __syncthreads();
    if (tid < 48) {
        int n = tid >> 4, b = tid & 15;
        float f1 = tanh_(pre2[(n * 3 + 0) * 16 + b]);
        float f2 = tanh_(pre2[(n * 3 + 1) * 16 + b]);
        float ti = sigm (pre2[(n * 3 + 2) * 16 + b]);
        float h = f1 + ti * (f2 - f1);
        h2s[((hp ^ 1) * 16 + b) * 3 + n] = h;
        out[((size_t)(gb + b) * TSTEPS + s) * 3 + n] = (n == 0) ? tanh_(h) : sigm(h);
    }
    __syncthreads();
}

__global__ void __launch_bounds__(NT, 1)
ncp_cfc_kernel(const float* __restrict__ features, const float* __restrict__ command,
               const float* __restrict__ l0W, const float* __restrict__ l0b,
               const float* __restrict__ l1W, const float* __restrict__ l1b,
               const float* __restrict__ l2W, const float* __restrict__ l2b,
               const float* __restrict__ m0, const float* __restrict__ m1,
               const float* __restrict__ m2,
               float* __restrict__ out, int out_size)
{
    extern __shared__ unsigned char smem[];
    float4* w0s  = (float4*)(smem + OFF_W0);
    float4* w1s  = (float4*)(smem + OFF_W1);
    float4* w2s  = (float4*)(smem + OFF_W2);
    float4* feat = (float4*)(smem + OFF_FEAT);
    float4* h0b  = (float4*)(smem + OFF_H0B);
    float4* xc1  = (float4*)(smem + OFF_XC1);
    float4* xc2  = (float4*)(smem + OFF_XC2);
    float*  pre0 = (float*)(smem + OFF_PRE0);
    float*  pre1 = (float*)(smem + OFF_PRE1);
    float*  pre2 = (float*)(smem + OFF_PRE2);
    float*  b0s  = (float*)(smem + OFF_B0);
    float*  b1s  = (float*)(smem + OFF_B1);
    float*  b2s  = (float*)(smem + OFF_B2);
    float*  h2s  = (float*)(smem + OFF_H2);

    const int tid  = threadIdx.x;
    const int cta  = blockIdx.x;
    const int tile = cta >> 4;
    const int r    = cta & 15;
    const int gb   = tile * 16;

    // neuron ownership (rebalanced: CTA15 light, pays for layer-2)
    int n0c, n0b, n1c, n1b;
    if (r < 12)      { n0c = 10; n0b = r * 10; }
    else if (r < 15) { n0c = 9;  n0b = 120 + (r - 12) * 9; }
    else             { n0c = 5;  n0b = 147; }
    if (r < 9)       { n1c = 7;  n1b = r * 7; }
    else if (r < 15) { n1c = 6;  n1b = 63 + (r - 9) * 6; }
    else             { n1c = 2;  n1b = 99; }
    const int NR0 = n0c * 3, NR1 = n1c * 3;

    int gen = g_gen[tile];

    // -------------- prologue: weights -> smem (masked, gate-merged) --------
    for (int i = tid; i < NR0 * W0_S; i += NT) {
        int row = i / W0_S, k = i - row * W0_S;
        int ln = row / 3, g = row - ln * 3, n = n0b + ln;
        float4 w;
        if (g < 2) {
            w = ((const float4*)(l0W + ((size_t)g * H0N + n) * 664))[k];
            float4 mk = ((const float4*)(m0 + (size_t)n * 664))[k];
            w.x *= mk.x; w.y *= mk.y; w.z *= mk.z; w.w *= mk.w;
        } else {
            float4 a = ((const float4*)(l0W + ((size_t)2 * H0N + n) * 664))[k];
            float4 c = ((const float4*)(l0W + ((size_t)3 * H0N + n) * 664))[k];
            w.x = a.x + c.x; w.y = a.y + c.y; w.z = a.z + c.z; w.w = a.w + c.w;
        }
        w0s[row * W0_S + k] = w;
    }
    for (int i = tid; i < NR1 * 264; i += NT) {
        int row = i / 264, k = i - row * 264;
        int ln = row / 3, g = row - ln * 3, n = n1b + ln;
        float w = 0.0f;
        if (k < 253) {
            if (g < 2) w = l1W[((size_t)g * H1N + n) * 253 + k] * m1[(size_t)n * 253 + k];
            else       w = l1W[((size_t)2 * H1N + n) * 253 + k] +
                           l1W[((size_t)3 * H1N + n) * 253 + k];
        }
        ((float*)w1s)[row * 264 + k] = w;
    }
    if (tid < NR0) {
        int ln = tid / 3, g = tid - ln * 3, n = n0b + ln;
        b0s[tid] = (g < 2) ? l0b[g * H0N + n] : (l0b[2 * H0N + n] + l0b[3 * H0N + n]);
    }
    if (tid < NR1) {
        int ln = tid / 3, g = tid - ln * 3, n = n1b + ln;
        b1s[tid] = (g < 2) ? l1b[g * H1N + n] : (l1b[2 * H1N + n] + l1b[3 * H1N + n]);
    }
    if (r == 15) {
        for (int i = tid; i < 9 * 104; i += NT) {
            int row = i / 104, k = i - row * 104;
            int n = row / 3, g = row - n * 3;
            float w;
            if (g < 2) w = l2W[(g * 3 + n) * 104 + k] * m2[n * 104 + k];
            else       w = l2W[(2 * 3 + n) * 104 + k] + l2W[(3 * 3 + n) * 104 + k];
            ((float*)w2s)[row * 104 + k] = w;
        }
        if (tid < 9) {
            int n = tid / 3, g = tid - n * 3;
            b2s[tid] = (g < 2) ? l2b[g * 3 + n] : (l2b[2 * 3 + n] + l2b[3 * 3 + n]);
        }
        if (tid < 96) h2s[tid] = 0.0f;
        if (tid < 144) {                       // zero h1 pads, all 3 bufs
            int bu = tid / 48, rem = tid - bu * 48, b = rem / 3, j = rem - b * 3;
            g_h1[bu][gb + b][101 + j] = 0.0f;
        }
    }
    for (int i = tid; i < n0c * 16; i += NT) { // h(-1) = 0 lives in buf 2
        int n = i >> 4, b = i & 15;
        g_h0[2][gb + b][n0b + n] = 0.0f;
    }
    for (int i = tid; i < n1c * 16; i += NT) {
        int n = i >> 4, b = i & 15;
        g_h1[2][gb + b][n1b + n] = 0.0f;
    }
    // prefetch features(t=0) into buffer 0
    for (int i = tid; i < 2048; i += NT) {
        int b = i >> 7, k = i & 127;
        const float* src = (k < 127)
            ? features + ((size_t)(gb + b) * TSTEPS + 0) * 508 + (k << 2)
            : command  + ((size_t)(gb + b) * TSTEPS + 0) * 4;
        cp16(&feat[(size_t)b * FEAT_S + k], src);
    }
    asm volatile("cp.async.commit_group;\n" ::: "memory");
    tile_barrier(tile, gen);                  // all init visible tile-wide

    int wr_i = 0, rd_i = 2;                   // h buffers: write t%3, read (t-1)%3
    const int hh = tid >> 8;                  // K-half
    const int rt = (tid >> 3) & 31;           // row slot
    const int bt = tid & 7;                   // batch slot (bt and bt+8)

    // ------------------------------ time loop ------------------------------
    for (int t = 0; t < TSTEPS; ++t) {
        const int p = t & 1;

        // A: issue prefetch(t+1), copy h0(t-1) to smem, drain prefetch(t)
        if (t + 1 < TSTEPS) {
            for (int i = tid; i < 2048; i += NT) {
                int b = i >> 7, k = i & 127;
                const float* src = (k < 127)
                    ? features + ((size_t)(gb + b) * TSTEPS + (t + 1)) * 508 + (k << 2)
                    : command  + ((size_t)(gb + b) * TSTEPS + (t + 1)) * 4;
                cp16(&feat[(size_t)((p ^ 1) * 16 + b) * FEAT_S + k], src);
            }
            asm volatile("cp.async.commit_group;\n" ::: "memory");
        }
        for (int i = tid; i < 608; i += NT) {
            int b = i / 38, k = i - b * 38;
            h0b[b * H0B_S + k] = __ldcg((const float4*)&g_h0[rd_i][gb + b][0] + k);
        }
        if (t + 1 < TSTEPS) asm volatile("cp.async.wait_group 1;\n" ::: "memory");
        else                asm volatile("cp.async.wait_group 0;\n" ::: "memory");
        __syncthreads();

        // B: layer-0 dots (K-split halves)
        if (rt < NR0) {
            const float4* __restrict__ wr = w0s + rt * W0_S;
            const float4* __restrict__ x0 = feat + (size_t)(p * 16 + bt) * FEAT_S;
            const float4* __restrict__ x1 = x0 + 8 * FEAT_S;
            const float4* __restrict__ h0 = h0b + bt * H0B_S;
            const float4* __restrict__ h1p = h0 + 8 * H0B_S;
            float4 a = {0.f,0.f,0.f,0.f}, c = {0.f,0.f,0.f,0.f};
            if (hh == 0) {
                #pragma unroll 2
                for (int k = 0; k < 83; ++k) {
                    float4 w = wr[k], u = x0[k], v = x1[k];
                    a.x = fmaf(w.x,u.x,a.x); a.y = fmaf(w.y,u.y,a.y);
                    a.z = fmaf(w.z,u.z,a.z); a.w = fmaf(w.w,u.w,a.w);
                    c.x = fmaf(w.x,v.x,c.x); c.y = fmaf(w.y,v.y,c.y);
                    c.z = fmaf(w.z,v.z,c.z); c.w = fmaf(w.w,v.w,c.w);
                }
            } else {
                #pragma unroll 2
                for (int k = 83; k < 128; ++k) {
                    float4 w = wr[k], u = x0[k], v = x1[k];
                    a.x = fmaf(w.x,u.x,a.x); a.y = fmaf(w.y,u.y,a.y);
                    a.z = fmaf(w.z,u.z,a.z); a.w = fmaf(w.w,u.w,a.w);
                    c.x = fmaf(w.x,v.x,c.x); c.y = fmaf(w.y,v.y,c.y);
                    c.z = fmaf(w.z,v.z,c.z); c.w = fmaf(w.w,v.w,c.w);
                }
                #pragma unroll 2
                for (int k = 0; k < 38; ++k) {
                    float4 w = wr[128 + k], u = h0[k], v = h1p[k];
                    a.x = fmaf(w.x,u.x,a.x); a.y = fmaf(w.y,u.y,a.y);
                    a.z = fmaf(w.z,u.z,a.z); a.w = fmaf(w.w,u.w,a.w);
                    c.x = fmaf(w.x,v.x,c.x); c.y = fmaf(w.y,v.y,c.y);
                    c.z = fmaf(w.z,v.z,c.z); c.w = fmaf(w.w,v.w,c.w);
                }
            }
            pre0[hh * 480 + rt * 16 + bt]     = (a.x + a.y) + (a.z + a.w);
            pre0[hh * 480 + rt * 16 + bt + 8] = (c.x + c.y) + (c.z + c.w);
        }
        __syncthreads();

        // C: combine layer 0 -> g_h0[wr]
        if (tid < n0c * 16) {
            int n = tid >> 4, b = tid & 15, row = n * 3;
            float f1 = tanh_(b0s[row]     + pre0[row * 16 + b]       + pre0[480 + row * 16 + b]);
            float f2 = tanh_(b0s[row + 1] + pre0[(row + 1) * 16 + b] + pre0[480 + (row + 1) * 16 + b]);
            float ti = sigm (b0s[row + 2] + pre0[(row + 2) * 16 + b] + pre0[480 + (row + 2) * 16 + b]);
            __stcg(&g_h0[wr_i][gb + b][n0b + n], f1 + ti * (f2 - f1));
        }
        tile_barrier(tile, gen);              // ONE barrier per step

        // D: CTA15 computes layer2(t-1) (pipelined one step behind)
        if (r == 15 && t > 0)
            layer2(t - 1, rd_i, gb, tid, xc2, pre2, w2s, b2s, h2s, out);

        // E: build xc1 = [h0(t) | h1(t-1) padded]
        for (int i = tid; i < 1024; i += NT) {
            int b = i >> 6, k = i & 63;
            float4 v = (k < 38)
                ? __ldcg((const float4*)&g_h0[wr_i][gb + b][0] + k)
                : __ldcg((const float4*)&g_h1[rd_i][gb + b][0] + (k - 38));
            xc1[b * XC1_S + k] = v;
        }
        __syncthreads();

        // F: layer-1 dots (K-split)
        if (rt < NR1) {
            const float4* __restrict__ wr = w1s + rt * W1_S;
            const float4* __restrict__ x0 = xc1 + bt * XC1_S;
            const float4* __restrict__ x1 = x0 + 8 * XC1_S;
            float4 a = {0.f,0.f,0.f,0.f}, c = {0.f,0.f,0.f,0.f};
            const int klo = hh * 32, khi = klo + 32;
            #pragma unroll 4
            for (int k = klo; k < khi; ++k) {
                float4 w = wr[k], u = x0[k], v = x1[k];
                a.x = fmaf(w.x,u.x,a.x); a.y = fmaf(w.y,u.y,a.y);
                a.z = fmaf(w.z,u.z,a.z); a.w = fmaf(w.w,u.w,a.w);
                c.x = fmaf(w.x,v.x,c.x); c.y = fmaf(w.y,v.y,c.y);
                c.z = fmaf(w.z,v.z,c.z); c.w = fmaf(w.w,v.w,c.w);
            }
            pre1[hh * 336 + rt * 16 + bt]     = (a.x + a.y) + (a.z + a.w);
            pre1[hh * 336 + rt * 16 + bt + 8] = (c.x + c.y) + (c.z + c.w);
        }
        __syncthreads();

        // G: combine layer 1 -> g_h1[wr]
        if (tid < n1c * 16) {
            int n = tid >> 4, b = tid & 15, row = n * 3;
            float f1 = tanh_(b1s[row]     + pre1[row * 16 + b]       + pre1[336 + row * 16 + b]);
            float f2 = tanh_(b1s[row + 1] + pre1[(row + 1) * 16 + b] + pre1[336 + (row + 1) * 16 + b]);
            float ti = sigm (b1s[row + 2] + pre1[(row + 2) * 16 + b] + pre1[336 + (row + 2) * 16 + b]);
            __stcg(&g_h1[wr_i][gb + b][n1b + n], f1 + ti * (f2 - f1));
        }

        rd_i = wr_i;
        wr_i = (wr_i == 2) ? 0 : wr_i + 1;
    }

    // flush deferred layer2(511), then epilogue hx
    tile_barrier(tile, gen);
    if (r == 15)
        layer2(TSTEPS - 1, rd_i, gb, tid, xc2, pre2, w2s, b2s, h2s, out);

    if (out_size >= 229376) {
        float* hx = out + (size_t)128 * TSTEPS * 3;
        for (int i = tid; i < n0c * 16; i += NT) {
            int n = i >> 4, b = i & 15;
            hx[(size_t)(gb + b) * 256 + n0b + n] = __ldcg(&g_h0[rd_i][gb + b][n0b + n]);
        }
        for (int i = tid; i < n1c * 16; i += NT) {
            int n = i >> 4, b = i & 15;
            hx[(size_t)(gb + b) * 256 + 152 + n1b + n] = __ldcg(&g_h1[rd_i][gb + b][n1b + n]);
        }
        if (r == 15 && tid < 48) {
            int b = tid / 3, j = tid - b * 3;
            hx[(size_t)(gb + b) * 256 + 253 + j] = h2s[(1 * 16 + b) * 3 + j];
        }
    }
}

extern "C" void kernel_launch(void* const* d_in, const int* in_sizes, int n_in,
                              void* d_out, int out_size) {
    (void)in_sizes; (void)n_in;
    cudaFuncSetAttribute(ncp_cfc_kernel,
                         cudaFuncAttributeMaxDynamicSharedMemorySize, SMEM_BYTES);
    ncp_cfc_kernel<<<128, NT, SMEM_BYTES>>>(
        (const float*)d_in[0], (const float*)d_in[1],
        (const float*)d_in[2], (const float*)d_in[3],
        (const float*)d_in[4], (const float*)d_in[5],
        (const float*)d_in[6], (const float*)d_in[7],
        (const float*)d_in[8], (const float*)d_in[9],
        (const float*)d_in[10],
        (float*)d_out, out_size);
}